// round 4
// baseline (speedup 1.0000x reference)
#include <cuda_runtime.h>

// Problem constants (fixed by the dataset)
#define HG   256
#define WG   256
#define BB   2
#define CC   4
#define NN   1024
#define TILE 16                // 16x16 grid cells per CTA
#define TPB  256               // one thread per cell
#define TILES_X (WG / TILE)    // 16
#define TILES_Y (HG / TILE)    // 16
#define PPT  (NN / TPB)        // 4 points per thread
#define CAP  512               // survivor capacity (expected ~32)

// half-diagonal of a 16x16-cell tile: (TILE/2)/256 * sqrt(2)
#define RT 0.0441941738f

__device__ __forceinline__ void upd(float d2, int n, float& best, int& bestN)
{
    // order-independent argmin with first-index tie-break (jnp.argmin rule)
    bool better = (d2 < best) || (d2 == best && n < bestN);
    best  = better ? d2 : best;
    bestN = better ? n  : bestN;
}

__global__ __launch_bounds__(TPB)
void nn_tile_kernel(const float* __restrict__ R_pc,   // [B, C, N]
                    const float* __restrict__ XY_pc,  // [B, 2, N]
                    float* __restrict__ out)          // [B, C, H, W]
{
    __shared__ float4 sv[CAP];     // survivors: (-2*px, -2*py, pn2, idx-bits)
    __shared__ int    s_cnt;
    __shared__ float  s_warpmin[TPB / 32];

    const int tile = blockIdx.x;           // 0..255
    const int b    = blockIdx.y;           // 0..1
    const int tj   = tile % TILES_X;
    const int ti   = tile / TILES_X;
    const int t    = threadIdx.x;

    const float inv = 1.0f / 256.0f;
    const float cx  = (float)(tj * TILE + TILE / 2) * inv;  // tile center
    const float cy  = (float)(ti * TILE + TILE / 2) * inv;

    const float* Xb = XY_pc + b * 2 * NN;

    // ---- Load 4 points per thread ONCE (two LDG.128), keep in registers ----
    const int nbase = t * PPT;
    float4 px4 = *(const float4*)(Xb + nbase);
    float4 py4 = *(const float4*)(Xb + NN + nbase);
    float px[PPT] = {px4.x, px4.y, px4.z, px4.w};
    float py[PPT] = {py4.x, py4.y, py4.z, py4.w};

    // ---- Phase 1: min distance^2 from tile center (register data) ----
    float d2c[PPT];
    float dmin = 3.4e38f;
    #pragma unroll
    for (int k = 0; k < PPT; k++) {
        float dx = px[k] - cx, dy = py[k] - cy;
        d2c[k] = fmaf(dx, dx, dy * dy);
        dmin = fminf(dmin, d2c[k]);
    }
    #pragma unroll
    for (int o = 16; o > 0; o >>= 1)
        dmin = fminf(dmin, __shfl_xor_sync(0xffffffffu, dmin, o));
    if ((t & 31) == 0) s_warpmin[t >> 5] = dmin;
    if (t == 0) s_cnt = 0;
    __syncthreads();

    float rmin = s_warpmin[0];
    #pragma unroll
    for (int w = 1; w < TPB / 32; w++) rmin = fminf(rmin, s_warpmin[w]);

    // cull radius: r_min + 2*r_tile (+ fp safety margin). Exact bound:
    // a point farther from the center cannot be nearest for any cell here.
    float Rrad = sqrtf(rmin) + 2.0f * RT + 1e-3f;
    float R2   = Rrad * Rrad;

    // ---- Phase 2: compact survivors into shared memory (from registers) ----
    // Store -2*px, -2*py (exact power-of-2 scaling -> d2 stays bitwise equal
    // to the reference formula pn2 - 2*fma(gy,py, gx*px)).
    #pragma unroll
    for (int k = 0; k < PPT; k++) {
        if (d2c[k] <= R2) {
            int slot = atomicAdd(&s_cnt, 1);
            if (slot < CAP) {
                float pn2 = __fadd_rn(__fmul_rn(px[k], px[k]),
                                      __fmul_rn(py[k], py[k]));
                sv[slot] = make_float4(-2.0f * px[k], -2.0f * py[k], pn2,
                                       __int_as_float(nbase + k));
            }
        }
    }
    __syncthreads();
    const int M = s_cnt;

    // ---- Phase 3: per-cell argmin, 4 independent accumulators ----
    const int jl = t & (TILE - 1);
    const int il = t >> 4;
    const int gi = ti * TILE + il;
    const int gj = tj * TILE + jl;
    const float gx = ((float)gj + 0.5f) * inv;
    const float gy = ((float)gi + 0.5f) * inv;

    float best  = 3.4e38f;
    int   bestN = 0;

    if (M <= CAP) {
        float b0 = 3.4e38f, b1 = 3.4e38f, b2 = 3.4e38f, b3 = 3.4e38f;
        int   n0 = 0, n1 = 0, n2 = 0, n3 = 0;
        int m = 0;
        for (; m + 4 <= M; m += 4) {
            float4 p0 = sv[m], p1 = sv[m+1], p2 = sv[m+2], p3 = sv[m+3];
            // d2 = pn2 + (-2)*fma(gy,py, gx*px)  (bitwise == reference)
            float d0 = __fadd_rn(p0.z, fmaf(gy, p0.y, __fmul_rn(gx, p0.x)));
            float d1 = __fadd_rn(p1.z, fmaf(gy, p1.y, __fmul_rn(gx, p1.x)));
            float d2_ = __fadd_rn(p2.z, fmaf(gy, p2.y, __fmul_rn(gx, p2.x)));
            float d3 = __fadd_rn(p3.z, fmaf(gy, p3.y, __fmul_rn(gx, p3.x)));
            upd(d0, __float_as_int(p0.w), b0, n0);
            upd(d1, __float_as_int(p1.w), b1, n1);
            upd(d2_, __float_as_int(p2.w), b2, n2);
            upd(d3, __float_as_int(p3.w), b3, n3);
        }
        for (; m < M; m++) {
            float4 p  = sv[m];
            float d  = __fadd_rn(p.z, fmaf(gy, p.y, __fmul_rn(gx, p.x)));
            upd(d, __float_as_int(p.w), b0, n0);
        }
        // merge (same lexicographic rule -> order-independent)
        upd(b1, n1, b0, n0);
        upd(b2, n2, b0, n0);
        upd(b3, n3, b0, n0);
        best = b0; bestN = n0;
    } else {
        // overflow fallback (never expected for this dataset): full scan
        for (int n = 0; n < NN; n++) {
            float qx = Xb[n], qy = Xb[NN + n];
            float pn2 = __fadd_rn(__fmul_rn(qx, qx), __fmul_rn(qy, qy));
            float dot = fmaf(gy, qy, __fmul_rn(gx, qx));
            float d2  = __fadd_rn(pn2, -2.0f * dot);
            upd(d2, n, best, bestN);
        }
    }

    // ---- Gather channel values and write output ----
    const float* Rb = R_pc + b * CC * NN;
    float* ob = out + ((size_t)b * CC * HG * WG) + (size_t)gi * WG + gj;
    #pragma unroll
    for (int c = 0; c < CC; c++)
        ob[(size_t)c * HG * WG] = Rb[c * NN + bestN];
}

extern "C" void kernel_launch(void* const* d_in, const int* in_sizes, int n_in,
                              void* d_out, int out_size)
{
    (void)in_sizes; (void)n_in; (void)out_size;
    const float* R_pc  = (const float*)d_in[0];  // [2,4,1024]
    const float* XY_pc = (const float*)d_in[1];  // [2,2,1024]
    float* out = (float*)d_out;                  // [2,4,256,256]

    dim3 grid(TILES_X * TILES_Y, BB);
    nn_tile_kernel<<<grid, TPB>>>(R_pc, XY_pc, out);
}

// round 7
// speedup vs baseline: 1.1507x; 1.1507x over previous
#include <cuda_runtime.h>

// Problem constants (fixed by the dataset)
#define HG   256
#define WG   256
#define BB   2
#define CC   4
#define NN   1024
#define TILE 16                // 16x16 grid cells per CTA
#define TPB  256               // one thread per cell
#define TILES_X (WG / TILE)    // 16
#define TILES_Y (HG / TILE)    // 16
#define PPT  (NN / TPB)        // 4 points per thread
#define QCAP 128               // per-quadrant survivor capacity (expected ~10)

// max distance from an 8x8 quadrant's center to any of its cell centers:
// sqrt(3.5^2+3.5^2)/256
#define RQ 0.0193352f

__global__ __launch_bounds__(TPB)
void nn_tile_kernel(const float* __restrict__ R_pc,   // [B, C, N]
                    const float* __restrict__ XY_pc,  // [B, 2, N]
                    float* __restrict__ out)          // [B, C, H, W]
{
    __shared__ float4 sv[4][QCAP];   // per-quadrant survivors (px,py,pn2,idx)
    __shared__ int    s_cnt[4];
    __shared__ float4 s_wq[TPB / 32]; // per-warp quadrant minima

    const int tile = blockIdx.x;           // 0..255
    const int b    = blockIdx.y;           // 0..1
    const int tj   = tile % TILES_X;
    const int ti   = tile / TILES_X;
    const int t    = threadIdx.x;

    const float inv = 1.0f / 256.0f;
    // quadrant centers: q = qi*2 + qj, center = (tj*16 + qj*8 + 4, ti*16 + qi*8 + 4)/256
    float qcx[4], qcy[4];
    #pragma unroll
    for (int q = 0; q < 4; q++) {
        qcx[q] = (float)(tj * TILE + (q & 1) * 8 + 4) * inv;
        qcy[q] = (float)(ti * TILE + (q >> 1) * 8 + 4) * inv;
    }

    const float* Xb = XY_pc + b * 2 * NN;

    // ---- Load 4 points per thread ONCE (two LDG.128), keep in registers ----
    const int nbase = t * PPT;
    float4 px4 = *(const float4*)(Xb + nbase);
    float4 py4 = *(const float4*)(Xb + NN + nbase);
    float px[PPT] = {px4.x, px4.y, px4.z, px4.w};
    float py[PPT] = {py4.x, py4.y, py4.z, py4.w};

    // ---- Phase 1: d2 from each point to each quadrant center; block min ----
    float d2q[4 * PPT];
    float mq[4] = {3.4e38f, 3.4e38f, 3.4e38f, 3.4e38f};
    #pragma unroll
    for (int k = 0; k < PPT; k++) {
        #pragma unroll
        for (int q = 0; q < 4; q++) {
            float dx = px[k] - qcx[q], dy = py[k] - qcy[q];
            float d2 = fmaf(dx, dx, dy * dy);
            d2q[q * PPT + k] = d2;
            mq[q] = fminf(mq[q], d2);
        }
    }
    // 4 interleaved warp min-reductions (independent shfl chains)
    #pragma unroll
    for (int o = 16; o > 0; o >>= 1) {
        #pragma unroll
        for (int q = 0; q < 4; q++)
            mq[q] = fminf(mq[q], __shfl_xor_sync(0xffffffffu, mq[q], o));
    }
    if ((t & 31) == 0)
        s_wq[t >> 5] = make_float4(mq[0], mq[1], mq[2], mq[3]);
    if (t < 4) s_cnt[t] = 0;
    __syncthreads();

    float rq[4] = {3.4e38f, 3.4e38f, 3.4e38f, 3.4e38f};
    #pragma unroll
    for (int w = 0; w < TPB / 32; w++) {
        float4 v = s_wq[w];
        rq[0] = fminf(rq[0], v.x);
        rq[1] = fminf(rq[1], v.y);
        rq[2] = fminf(rq[2], v.z);
        rq[3] = fminf(rq[3], v.w);
    }
    // exact cull bound per quadrant: a point with dist(qcenter,p) >
    // rmin_q + 2*RQ cannot be nearest for any cell in that quadrant.
    float R2q[4];
    #pragma unroll
    for (int q = 0; q < 4; q++) {
        float Rr = sqrtf(rq[q]) + 2.0f * RQ + 1e-3f;
        R2q[q] = Rr * Rr;
    }

    // ---- Phase 2: compact survivors into per-quadrant lists ----
    #pragma unroll
    for (int k = 0; k < PPT; k++) {
        float pn2 = __fadd_rn(__fmul_rn(px[k], px[k]),
                              __fmul_rn(py[k], py[k]));
        #pragma unroll
        for (int q = 0; q < 4; q++) {
            if (d2q[q * PPT + k] <= R2q[q]) {
                int slot = atomicAdd(&s_cnt[q], 1);
                if (slot < QCAP)
                    sv[q][slot] = make_float4(px[k], py[k], pn2,
                                              __int_as_float(nbase + k));
            }
        }
    }
    __syncthreads();

    // ---- Phase 3: per-cell argmin over this cell's quadrant list ----
    const int jl = t & (TILE - 1);
    const int il = t >> 4;
    const int gi = ti * TILE + il;
    const int gj = tj * TILE + jl;
    const int quad = ((il >> 3) << 1) | (jl >> 3);
    const float gx = ((float)gj + 0.5f) * inv;
    const float gy = ((float)gi + 0.5f) * inv;

    float best  = 3.4e38f;
    int   bestN = 0;
    const int M = s_cnt[quad];

    if (M <= QCAP) {
        const float4* lst = sv[quad];
        for (int m = 0; m < M; m++) {
            float4 p  = lst[m];
            // mirror reference: d2 = pn2 - 2*fma(gy,py, gx*px)
            float dot = fmaf(gy, p.y, __fmul_rn(gx, p.x));
            float d2  = __fadd_rn(p.z, -2.0f * dot);
            int   n   = __float_as_int(p.w);
            // order-independent argmin, first-index tie-break (jnp.argmin rule)
            if (d2 < best || (d2 == best && n < bestN)) {
                best  = d2;
                bestN = n;
            }
        }
    } else {
        // overflow fallback (never expected for this dataset): full scan
        for (int n = 0; n < NN; n++) {
            float qx = Xb[n], qy = Xb[NN + n];
            float pn2 = __fadd_rn(__fmul_rn(qx, qx), __fmul_rn(qy, qy));
            float dot = fmaf(gy, qy, __fmul_rn(gx, qx));
            float d2  = __fadd_rn(pn2, -2.0f * dot);
            if (d2 < best || (d2 == best && n < bestN)) {
                best  = d2;
                bestN = n;
            }
        }
    }

    // ---- Gather channel values and write output ----
    const float* Rb = R_pc + b * CC * NN;
    float* ob = out + ((size_t)b * CC * HG * WG) + (size_t)gi * WG + gj;
    #pragma unroll
    for (int c = 0; c < CC; c++)
        ob[(size_t)c * HG * WG] = Rb[c * NN + bestN];
}

extern "C" void kernel_launch(void* const* d_in, const int* in_sizes, int n_in,
                              void* d_out, int out_size)
{
    (void)in_sizes; (void)n_in; (void)out_size;
    const float* R_pc  = (const float*)d_in[0];  // [2,4,1024]
    const float* XY_pc = (const float*)d_in[1];  // [2,2,1024]
    float* out = (float*)d_out;                  // [2,4,256,256]

    dim3 grid(TILES_X * TILES_Y, BB);
    nn_tile_kernel<<<grid, TPB>>>(R_pc, XY_pc, out);
}